// round 8
// baseline (speedup 1.0000x reference)
#include <cuda_runtime.h>
#include <cuda_fp16.h>
#include <math.h>

#define NN 100000
#define EE 5000000
#define CAP 128                     // bucket capacity; P(deg>=128) ~ 1e-18/node

// Scratch (no allocations allowed).
__device__ __align__(16) float g_agg[NN * 16];
__device__ __align__(16) float g_h1[NN * 16];
__device__ __align__(16) float g_h2[NN * 16];
__device__ __align__(16) __half g_xh[NN * 8];    // fp16 shadow of x
__device__ __align__(16) __half g_h1h[NN * 16];  // fp16 shadow of raw y1
__device__ __align__(16) __half g_h2h[NN * 16];  // fp16 shadow of raw y2
__device__ float g_stats[96];       // 3 layers x (16 sum | 16 sumsq)
__device__ int   g_cnt[NN];         // per-node degree counters
__device__ int   g_bucket[NN * CAP];

// ---------------------------------------------------------------------------
// zero: counters + BN stats + fp16 conversion of x (8 features/node).
// ---------------------------------------------------------------------------
__global__ void zero_kernel(const float* __restrict__ x) {
    int i = blockIdx.x * blockDim.x + threadIdx.x;
    if (i < 96) g_stats[i] = 0.0f;
    if (i < NN) {
        g_cnt[i] = 0;
        float4 v0 = __ldg((const float4*)x + i * 2);
        float4 v1 = __ldg((const float4*)x + i * 2 + 1);
        __half2 h[4];
        h[0] = __floats2half2_rn(v0.x, v0.y);
        h[1] = __floats2half2_rn(v0.z, v0.w);
        h[2] = __floats2half2_rn(v1.x, v1.y);
        h[3] = __floats2half2_rn(v1.z, v1.w);
        ((uint4*)g_xh)[i] = *(uint4*)h;
    }
}

// ---------------------------------------------------------------------------
// Bucket fill: bucket[dst*CAP + cnt[dst]++] = src. 4 edges/thread.
// ---------------------------------------------------------------------------
__global__ void fill_kernel(const int* __restrict__ src, const int* __restrict__ dst) {
    int t = blockIdx.x * blockDim.x + threadIdx.x;
    if (t >= EE / 4) return;
    int4 s4 = ((const int4*)src)[t];
    int4 d4 = ((const int4*)dst)[t];
    int ss[4] = {s4.x, s4.y, s4.z, s4.w};
    int dd[4] = {d4.x, d4.y, d4.z, d4.w};
#pragma unroll
    for (int j = 0; j < 4; j++) {
        int pos = atomicAdd(&g_cnt[dd[j]], 1);
        if (pos < CAP) g_bucket[dd[j] * CAP + pos] = ss[j];
    }
}

// ---------------------------------------------------------------------------
// fp16 bucket gather: one warp per node. C = 16B chunks per feature row
// (1 for 8 features, 2 for 16). Lane (g, c): group g strides edges, chunk c.
// Each 16B load carries 8 halves -> 8 fp32 accumulators. Unroll x4.
// ---------------------------------------------------------------------------
__device__ __forceinline__ void acc8(float* a, uint4 u) {
    __half2* h = (__half2*)&u;
#pragma unroll
    for (int j = 0; j < 4; j++) {
        float2 f = __half22float2(h[j]);
        a[2 * j] += f.x;
        a[2 * j + 1] += f.y;
    }
}

template <int C>
__global__ void gather_kernel(const __half* __restrict__ xh, float* __restrict__ agg) {
    const int NG = 32 / C;
    int gw = (blockIdx.x * blockDim.x + threadIdx.x) >> 5;
    if (gw >= NN) return;
    int lane = threadIdx.x & 31;
    int c = lane & (C - 1);
    int g = lane / C;
    int n = min(__ldg(&g_cnt[gw]), CAP);
    const int* bk = g_bucket + (size_t)gw * CAP;
    const uint4* xf = (const uint4*)xh;
    float a0[8] = {0, 0, 0, 0, 0, 0, 0, 0};
    float a1[8] = {0, 0, 0, 0, 0, 0, 0, 0};
    int e = g;
    for (; e + 3 * NG < n; e += 4 * NG) {
        int s0 = __ldg(bk + e);
        int s1 = __ldg(bk + e + NG);
        int s2 = __ldg(bk + e + 2 * NG);
        int s3 = __ldg(bk + e + 3 * NG);
        uint4 u0 = __ldg(xf + (size_t)s0 * C + c);
        uint4 u1 = __ldg(xf + (size_t)s1 * C + c);
        uint4 u2 = __ldg(xf + (size_t)s2 * C + c);
        uint4 u3 = __ldg(xf + (size_t)s3 * C + c);
        acc8(a0, u0); acc8(a1, u1); acc8(a0, u2); acc8(a1, u3);
    }
    for (; e < n; e += NG) {
        int s = __ldg(bk + e);
        acc8(a0, __ldg(xf + (size_t)s * C + c));
    }
#pragma unroll
    for (int j = 0; j < 8; j++) a0[j] += a1[j];
#pragma unroll
    for (int off = C; off < 32; off <<= 1)
#pragma unroll
        for (int j = 0; j < 8; j++) a0[j] += __shfl_xor_sync(0xffffffffu, a0[j], off);
    if (lane < C) {
        float4* ap = (float4*)agg + (size_t)gw * (2 * C) + c * 2;
        ap[0] = make_float4(a0[0], a0[1], a0[2], a0[3]);
        ap[1] = make_float4(a0[4], a0[5], a0[6], a0[7]);
    }
}

// ---------------------------------------------------------------------------
// Fused node update, thread-coarsened x2. If PREVBN: fold previous BN affine:
// x = sc*xin+sh, agg_bn = sc*agg + deg*sh. Then GIN MLP + residual.
// Writes fp32 y (+ optional fp16 shadow). Accumulates BN stats (amortized
// shuffle reduction over the 2 nodes). ACT: 0 = LeakyReLU(0.01), 1 = ReLU.
// ---------------------------------------------------------------------------
template <int WIN, int ACT, int PREVBN, int WH>
__global__ void node_kernel(const float* __restrict__ xin,
                            const float* __restrict__ agg,
                            const float* __restrict__ epsp,
                            const float* __restrict__ w1, const float* __restrict__ b1,
                            const float* __restrict__ w2, const float* __restrict__ b2,
                            const float* __restrict__ rw, const float* __restrict__ rb,
                            float* __restrict__ y, __half* __restrict__ yh,
                            float* __restrict__ stats,
                            const float* __restrict__ pstats,
                            const float* __restrict__ pg, const float* __restrict__ pbe) {
    __shared__ float s_w1[WIN * 16];
    __shared__ float s_w2[256];
    __shared__ float s_rw[WIN * 16];
    __shared__ float s_b[48];
    __shared__ float s_sum[16], s_sq[16];
    __shared__ float s_sc[16], s_sh[16];

    int tid = threadIdx.x;
    for (int i = tid; i < WIN * 16; i += blockDim.x) { s_w1[i] = w1[i]; s_rw[i] = rw[i]; }
    for (int i = tid; i < 256; i += blockDim.x) s_w2[i] = w2[i];
    if (tid < 16) {
        s_b[tid] = b1[tid]; s_b[16 + tid] = b2[tid]; s_b[32 + tid] = rb[tid];
        s_sum[tid] = 0.0f; s_sq[tid] = 0.0f;
        if (PREVBN) {
            const float invN = 1.0f / (float)NN;
            float mu = pstats[tid] * invN;
            float var = pstats[16 + tid] * invN - mu * mu;
            float sc = pg[tid] * rsqrtf(var + 1e-5f);
            s_sc[tid] = sc;
            s_sh[tid] = pbe[tid] - sc * mu;
        }
    }
    __syncthreads();

    float ep = 1.0f + epsp[0];
    float lsum[16], lsq[16];
#pragma unroll
    for (int o = 0; o < 16; o++) { lsum[o] = 0.0f; lsq[o] = 0.0f; }

    int base = blockIdx.x * (blockDim.x * 2) + tid;
#pragma unroll
    for (int r = 0; r < 2; r++) {
        int i = base + r * blockDim.x;
        if (i >= NN) continue;
        float xr[WIN], hp[WIN];
        const float4* xp = (const float4*)(xin + (size_t)i * WIN);
        const float4* ap = (const float4*)(agg + (size_t)i * WIN);
        float dg = PREVBN ? (float)min(__ldg(&g_cnt[i]), CAP) : 0.0f;
#pragma unroll
        for (int k = 0; k < WIN / 4; k++) {
            float4 xv = xp[k];
            float4 av = ap[k];
            float xs[4] = {xv.x, xv.y, xv.z, xv.w};
            float as[4] = {av.x, av.y, av.z, av.w};
#pragma unroll
            for (int j = 0; j < 4; j++) {
                int f = 4 * k + j;
                float xx, aa;
                if (PREVBN) {
                    float sc = s_sc[f], sh = s_sh[f];
                    xx = fmaf(sc, xs[j], sh);
                    aa = fmaf(sc, as[j], dg * sh);
                } else {
                    xx = xs[j];
                    aa = as[j];
                }
                xr[f] = xx;
                hp[f] = fmaf(ep, xx, aa);
            }
        }
        float z[16];
#pragma unroll
        for (int o = 0; o < 16; o++) {
            float t = s_b[o];
#pragma unroll
            for (int k = 0; k < WIN; k++) t = fmaf(hp[k], s_w1[k * 16 + o], t);
            z[o] = (ACT == 0) ? (t > 0.0f ? t : 0.01f * t) : fmaxf(t, 0.0f);
        }
        float yv[16];
#pragma unroll
        for (int o = 0; o < 16; o++) {
            float t = s_b[16 + o] + s_b[32 + o];
#pragma unroll
            for (int k = 0; k < 16; k++) t = fmaf(z[k], s_w2[k * 16 + o], t);
#pragma unroll
            for (int k = 0; k < WIN; k++) t = fmaf(xr[k], s_rw[k * 16 + o], t);
            yv[o] = t;
            lsum[o] += t;
            lsq[o] = fmaf(t, t, lsq[o]);
        }
        float4* yp = (float4*)(y + (size_t)i * 16);
#pragma unroll
        for (int k = 0; k < 4; k++)
            yp[k] = make_float4(yv[4 * k], yv[4 * k + 1], yv[4 * k + 2], yv[4 * k + 3]);
        if (WH) {
            __half2 hv[8];
#pragma unroll
            for (int k = 0; k < 8; k++) hv[k] = __floats2half2_rn(yv[2 * k], yv[2 * k + 1]);
            uint4* hp4 = (uint4*)(yh + (size_t)i * 16);
            hp4[0] = ((uint4*)hv)[0];
            hp4[1] = ((uint4*)hv)[1];
        }
    }

    // Amortized BN stat reduction: butterfly over the warp, then shared+global.
#pragma unroll
    for (int o = 0; o < 16; o++) {
        float v = lsum[o], q = lsq[o];
#pragma unroll
        for (int off = 16; off; off >>= 1) {
            v += __shfl_xor_sync(0xffffffffu, v, off);
            q += __shfl_xor_sync(0xffffffffu, q, off);
        }
        if ((tid & 31) == 0) { atomicAdd(&s_sum[o], v); atomicAdd(&s_sq[o], q); }
    }
    __syncthreads();
    if (tid < 16) {
        atomicAdd(&stats[tid], s_sum[tid]);
        atomicAdd(&stats[16 + tid], s_sq[tid]);
    }
}

// ---------------------------------------------------------------------------
// BatchNorm finalize (in place) — final output only.
// ---------------------------------------------------------------------------
__global__ void bn_kernel(float* __restrict__ y, const float* __restrict__ stats,
                          const float* __restrict__ g, const float* __restrict__ be) {
    int t = blockIdx.x * blockDim.x + threadIdx.x;
    if (t >= NN * 4) return;
    int f0 = (t & 3) * 4;
    float4 v = ((float4*)y)[t];
    float vv[4] = {v.x, v.y, v.z, v.w};
    const float invN = 1.0f / (float)NN;
    float out[4];
#pragma unroll
    for (int j = 0; j < 4; j++) {
        int f = f0 + j;
        float mu = __ldg(stats + f) * invN;
        float var = __ldg(stats + 16 + f) * invN - mu * mu;
        float sc = __ldg(g + f) * rsqrtf(var + 1e-5f);
        out[j] = (vv[j] - mu) * sc + __ldg(be + f);
    }
    ((float4*)y)[t] = make_float4(out[0], out[1], out[2], out[3]);
}

// ---------------------------------------------------------------------------
// kernel_launch: 9 launches.
// ---------------------------------------------------------------------------
extern "C" void kernel_launch(void* const* d_in, const int* in_sizes, int n_in,
                              void* d_out, int out_size) {
    const float* x    = (const float*)d_in[0];
    const int*   ei   = (const int*)d_in[1];
    const int*   src  = ei;
    const int*   dst  = ei + EE;
    const float* eps1 = (const float*)d_in[2];
    const float* w11  = (const float*)d_in[3];
    const float* b11  = (const float*)d_in[4];
    const float* w12  = (const float*)d_in[5];
    const float* b12  = (const float*)d_in[6];
    const float* rw1  = (const float*)d_in[7];
    const float* rb1  = (const float*)d_in[8];
    const float* g1   = (const float*)d_in[9];
    const float* be1  = (const float*)d_in[10];
    const float* eps2 = (const float*)d_in[11];
    const float* w21  = (const float*)d_in[12];
    const float* b21  = (const float*)d_in[13];
    const float* w22  = (const float*)d_in[14];
    const float* b22  = (const float*)d_in[15];
    const float* rw2  = (const float*)d_in[16];
    const float* rb2  = (const float*)d_in[17];
    const float* g2   = (const float*)d_in[18];
    const float* be2  = (const float*)d_in[19];
    const float* eps3 = (const float*)d_in[20];
    const float* w31  = (const float*)d_in[21];
    const float* b31  = (const float*)d_in[22];
    const float* w32  = (const float*)d_in[23];
    const float* b32  = (const float*)d_in[24];
    const float* rw3  = (const float*)d_in[25];
    const float* rb3  = (const float*)d_in[26];
    const float* g3   = (const float*)d_in[27];
    const float* be3  = (const float*)d_in[28];

    float *agg, *h1, *h2, *stats;
    __half *xh, *h1h, *h2h;
    cudaGetSymbolAddress((void**)&agg,   g_agg);
    cudaGetSymbolAddress((void**)&h1,    g_h1);
    cudaGetSymbolAddress((void**)&h2,    g_h2);
    cudaGetSymbolAddress((void**)&stats, g_stats);
    cudaGetSymbolAddress((void**)&xh,    g_xh);
    cudaGetSymbolAddress((void**)&h1h,   g_h1h);
    cudaGetSymbolAddress((void**)&h2h,   g_h2h);
    float* out = (float*)d_out;

    const int TB = 256;
    const int ge  = (EE / 4 + TB - 1) / TB;
    const int gn  = (NN + TB - 1) / TB;
    const int gn2 = (NN + TB * 2 - 1) / (TB * 2);
    const int gb  = (NN * 4 + TB - 1) / TB;
    const int gg  = (NN * 32 + TB - 1) / TB;   // warp per node

    // ---- build: counters+stats zero + x fp16 convert, then bucket fill ----
    zero_kernel<<<gn, TB>>>(x);
    fill_kernel<<<ge, TB>>>(src, dst);

    // ---- block 1: GIN(8->16->16, LeakyReLU) + residual; y1 stays RAW ----
    gather_kernel<1><<<gg, TB>>>(xh, agg);
    node_kernel<8, 0, 0, 1><<<gn2, TB>>>(x, agg, eps1, w11, b11, w12, b12, rw1, rb1,
                                         h1, h1h, stats, nullptr, nullptr, nullptr);

    // ---- block 2: gather raw y1 (fp16); node folds bn1 affine; y2 RAW ----
    gather_kernel<2><<<gg, TB>>>(h1h, agg);
    node_kernel<16, 1, 1, 1><<<gn2, TB>>>(h1, agg, eps2, w21, b21, w22, b22, rw2, rb2,
                                          h2, h2h, stats + 32, stats, g1, be1);

    // ---- block 3: gather raw y2 (fp16); node folds bn2 affine; final bn ----
    gather_kernel<2><<<gg, TB>>>(h2h, agg);
    node_kernel<16, 1, 1, 0><<<gn2, TB>>>(h2, agg, eps3, w31, b31, w32, b32, rw3, rb3,
                                          out, nullptr, stats + 64, stats + 32, g2, be2);
    bn_kernel<<<gb, TB>>>(out, stats + 64, g3, be3);
}